// round 7
// baseline (speedup 1.0000x reference)
#include <cuda_runtime.h>
#include <cuda_fp16.h>
#include <math.h>

#define NN   20000
#define EE   160000
#define FEE  500000
#define KHOP 3

// ---------------- scratch (static __device__, no allocations) ----------------
__device__ int     g_degi[NN];
__device__ int     g_cnt[NN];
__device__ float   g_deginv[NN];
__device__ int     g_rowptr[NN + 1];
__device__ int     g_bsum[96];
__device__ int     g_esrc[EE];
__device__ float   g_ew[EE];
__device__ float   g_temb[128 * 64];
__device__ float   g_Q[NN * 64];
__device__ float   g_Kp[2][NN * 64];
__device__ __align__(16) __half g_KVh[(size_t)NN * 128];   // per node: K[64] | V[64], fp16
__device__ __half2 g_Mh[2][(size_t)NN * 512];              // M in fp16, 512 half2 per node
__device__ float   g_hidden[NN * 64];

// ---------------- timestep-embedding table (128 distinct timesteps) ----------------
__global__ void __launch_bounds__(64)
k_temb(const float* __restrict__ Wt1, const float* __restrict__ bt1,
       const float* __restrict__ Wt2, const float* __restrict__ bt2) {
    __shared__ float se[64];
    __shared__ float s1[256];
    int ts = blockIdx.x;      // 0..127
    int j = threadIdx.x;      // 0..63
    float tsf = (float)ts * 31.25f;   // 4000/128
    {
        const float negLn = -logf(10000.0f) / 31.0f;
        int f = j & 31;
        float arg = tsf * expf(negLn * (float)f);
        se[j] = (j < 32) ? sinf(arg) : cosf(arg);
    }
    __syncthreads();
    for (int c = j; c < 256; c += 64) {
        float a = __ldg(bt1 + c);
        for (int k = 0; k < 64; k++) a = fmaf(se[k], __ldg(Wt1 + k * 256 + c), a);
        s1[c] = a / (1.0f + expf(-a));   // silu
    }
    __syncthreads();
    {
        float a = __ldg(bt2 + j);
        for (int k = 0; k < 256; k++) a = fmaf(s1[k], __ldg(Wt2 + k * 64 + j), a);
        g_temb[ts * 64 + j] = a;
    }
}

// ---------------- CSR build ----------------
__global__ void k_init() {
    int i = blockIdx.x * blockDim.x + threadIdx.x;
    if (i < NN) { g_degi[i] = 0; g_cnt[i] = 0; }
}

__global__ void k_hist(const int* __restrict__ col) {
    int e = blockIdx.x * blockDim.x + threadIdx.x;
    if (e < EE) atomicAdd(&g_degi[col[e]], 1);
}

// 79 blocks x 256: per-block exclusive scan -> g_rowptr (local), block totals -> g_bsum
__global__ void __launch_bounds__(256) k_scanA() {
    __shared__ int wsum[8];
    int t = threadIdx.x, b = blockIdx.x;
    int idx = b * 256 + t;
    int d = (idx < NN) ? g_degi[idx] : 0;
    int lane = t & 31, w = t >> 5;
    int v = d;
#pragma unroll
    for (int m = 1; m < 32; m <<= 1) {
        int o = __shfl_up_sync(0xFFFFFFFFu, v, m);
        if (lane >= m) v += o;
    }
    if (lane == 31) wsum[w] = v;
    __syncthreads();
    if (t == 0) {
        int run = 0;
#pragma unroll
        for (int i = 0; i < 8; i++) { int xx = wsum[i]; wsum[i] = run; run += xx; }
        g_bsum[b] = run;
    }
    __syncthreads();
    if (idx < NN) g_rowptr[idx] = v - d + wsum[w];
}

// 1 block x 128: exclusive scan of 79 block sums in place
__global__ void __launch_bounds__(128) k_scanB() {
    __shared__ int ws[4];
    int t = threadIdx.x;
    int v0 = (t < 79) ? g_bsum[t] : 0;
    int v = v0;
    int lane = t & 31, w = t >> 5;
#pragma unroll
    for (int m = 1; m < 32; m <<= 1) {
        int o = __shfl_up_sync(0xFFFFFFFFu, v, m);
        if (lane >= m) v += o;
    }
    if (lane == 31) ws[w] = v;
    __syncthreads();
    if (t == 0) {
        int run = 0;
#pragma unroll
        for (int i = 0; i < 4; i++) { int xx = ws[i]; ws[i] = run; run += xx; }
    }
    __syncthreads();
    if (t < 79) g_bsum[t] = v - v0 + ws[w];
}

// 79 blocks x 256: add block offsets, compute deginv, close rowptr
__global__ void __launch_bounds__(256) k_scanC() {
    int idx = blockIdx.x * 256 + threadIdx.x;
    if (idx < NN) {
        g_rowptr[idx] += g_bsum[blockIdx.x];
        int dg = g_degi[idx];
        g_deginv[idx] = dg > 0 ? 1.0f / (float)dg : 0.0f;
    }
    if (idx == 0) g_rowptr[NN] = EE;
}

__global__ void k_fill(const int* __restrict__ row, const int* __restrict__ col) {
    int e = blockIdx.x * blockDim.x + threadIdx.x;
    if (e < EE) {
        int c = col[e];
        int r = row[e];
        int p = atomicAdd(&g_cnt[c], 1);
        int pos = g_rowptr[c] + p;
        g_esrc[pos] = r;
        g_ew[pos] = g_deginv[r];   // norm = deg_inv[source]; deg over destinations
    }
}

// ---------------- fused node-feature pipeline ----------------
// block = 256 threads handles 64 nodes. Dynamic smem: sX[64*128] | sB[64*64]
__global__ void __launch_bounds__(256)
k_node(const float* __restrict__ x, const int* __restrict__ tsteps,
       const float* __restrict__ Wi, const float* __restrict__ bi,
       const float* __restrict__ WQ, const float* __restrict__ bQ,
       const float* __restrict__ WK, const float* __restrict__ bK,
       const float* __restrict__ WV, const float* __restrict__ bV,
       const float* __restrict__ hopwise) {
    extern __shared__ float sm[];
    float* sX = sm;               // 8192 floats
    float* sB = sm + 64 * 128;    // 4096 floats: h
    const int t = threadIdx.x;
    const int nb = blockIdx.x * 64;
    const int lane = t & 31, wid = t >> 5;

    // ---- load x tile (float4, coalesced) ----
    {
        const float4* xv = (const float4*)x;
        float4* sxv = (float4*)sX;
#pragma unroll
        for (int i = 0; i < 8; i++) {
            int idx = t + 256 * i;      // float4 index in tile (2048 total)
            int n = idx >> 5;           // 32 float4 per row
            int c4 = idx & 31;
            float4 v = make_float4(0.f, 0.f, 0.f, 0.f);
            if (nb + n < NN) v = __ldg(xv + (size_t)(nb + n) * 32 + c4);
            sxv[idx] = v;
        }
    }
    __syncthreads();

    // ---- h = relu(sX @ Wi + bi + temb[ts]) -> sB ----
    {
        float acc[8][2];
        {
            float2 b = __ldg((const float2*)bi + lane);
#pragma unroll
            for (int i = 0; i < 8; i++) { acc[i][0] = b.x; acc[i][1] = b.y; }
        }
        for (int k0 = 0; k0 < 128; k0 += 4) {
            float wv[4][2];
#pragma unroll
            for (int r = 0; r < 4; r++) {
                float2 w = __ldg((const float2*)(Wi + (k0 + r) * 64) + lane);
                wv[r][0] = w.x; wv[r][1] = w.y;
            }
#pragma unroll
            for (int i = 0; i < 8; i++) {
                float4 a = *(const float4*)(sX + (wid + 8 * i) * 128 + k0);
#pragma unroll
                for (int c = 0; c < 2; c++) {
                    acc[i][c] = fmaf(a.x, wv[0][c],
                                fmaf(a.y, wv[1][c],
                                fmaf(a.z, wv[2][c],
                                fmaf(a.w, wv[3][c], acc[i][c]))));
                }
            }
        }
#pragma unroll
        for (int i = 0; i < 8; i++) {
            int rowl = wid + 8 * i;
            int g = nb + rowl;
            int ts = (g < NN) ? __ldg(tsteps + g) : 0;
            const float2* te = (const float2*)(g_temb + ts * 64) + lane;
            float2 tv = *te;
#pragma unroll
            for (int c = 0; c < 2; c++) {
                float v = acc[i][c] + ((c == 0) ? tv.x : tv.y);
                v = fmaxf(v, 0.0f);
                sB[rowl * 64 + lane * 2 + c] = v;
            }
        }
    }
    __syncthreads();

    // ---- Q,K,V from h; write Q, Kf0 (fp32), K|V (fp16), hidden init ----
    {
        float aq[8][2], ak[8][2], av[8][2];
        {
            float2 bq = __ldg((const float2*)bQ + lane);
            float2 bk = __ldg((const float2*)bK + lane);
            float2 bv = __ldg((const float2*)bV + lane);
#pragma unroll
            for (int i = 0; i < 8; i++) {
                aq[i][0] = bq.x; aq[i][1] = bq.y;
                ak[i][0] = bk.x; ak[i][1] = bk.y;
                av[i][0] = bv.x; av[i][1] = bv.y;
            }
        }
        for (int k0 = 0; k0 < 64; k0 += 4) {
            float wq[4][2], wk[4][2], wvv[4][2];
#pragma unroll
            for (int r = 0; r < 4; r++) {
                float2 a1 = __ldg((const float2*)(WQ + (k0 + r) * 64) + lane);
                float2 a2 = __ldg((const float2*)(WK + (k0 + r) * 64) + lane);
                float2 a3 = __ldg((const float2*)(WV + (k0 + r) * 64) + lane);
                wq[r][0] = a1.x; wq[r][1] = a1.y;
                wk[r][0] = a2.x; wk[r][1] = a2.y;
                wvv[r][0] = a3.x; wvv[r][1] = a3.y;
            }
#pragma unroll
            for (int i = 0; i < 8; i++) {
                float4 a = *(const float4*)(sB + (wid + 8 * i) * 64 + k0);
#pragma unroll
                for (int c = 0; c < 2; c++) {
                    aq[i][c] = fmaf(a.x, wq[0][c], fmaf(a.y, wq[1][c], fmaf(a.z, wq[2][c], fmaf(a.w, wq[3][c], aq[i][c]))));
                    ak[i][c] = fmaf(a.x, wk[0][c], fmaf(a.y, wk[1][c], fmaf(a.z, wk[2][c], fmaf(a.w, wk[3][c], ak[i][c]))));
                    av[i][c] = fmaf(a.x, wvv[0][c], fmaf(a.y, wvv[1][c], fmaf(a.z, wvv[2][c], fmaf(a.w, wvv[3][c], av[i][c]))));
                }
            }
        }
        float hop0 = __ldg(hopwise);
#pragma unroll
        for (int i = 0; i < 8; i++) {
            int nl = wid + 8 * i;
            int g = nb + nl;
            if (g >= NN) continue;
#pragma unroll
            for (int c = 0; c < 2; c++) {
                int cc = lane * 2 + c;
                float q = aq[i][c]; q = (q > 0.f) ? q + 1.f : expf(q);
                float kk = ak[i][c]; kk = (kk > 0.f) ? kk + 1.f : expf(kk);
                float vv = av[i][c];
                g_Q[g * 64 + cc] = q;
                g_Kp[0][g * 64 + cc] = kk;
                g_hidden[g * 64 + cc] = vv * hop0;
                g_KVh[(size_t)g * 128 + cc] = __float2half(kk);
                g_KVh[(size_t)g * 128 + 64 + cc] = __float2half(vv);
            }
        }
    }
}

// ---------------- hop 0: rank-1 propagation (K,V gather; M never read) ----------------
// TWO warps per destination node; warp `half` owns global heads {2*half, 2*half+1}.
// Writes M1 -> g_Mh[1], Kf1 -> g_Kp[1]; hidden update with hop=0.
__global__ void __launch_bounds__(256)
k_prop1(const float* __restrict__ hopwise, const float* __restrict__ headwise) {
    int warp = (blockIdx.x * 256 + threadIdx.x) >> 5;
    int node = warp >> 1;
    int half = warp & 1;
    int lane = threadIdx.x & 31;
    if (node >= NN) return;
    int s = g_rowptr[node], e = g_rowptr[node + 1];
    const float* Kc = g_Kp[0];
    const int i_idx = lane >> 1;
    const int jb = (lane & 1) * 8;

    float acc[2][8];
#pragma unroll
    for (int u = 0; u < 2; u++)
#pragma unroll
        for (int c = 0; c < 8; c++) acc[u][c] = 0.f;
    float4 ack = make_float4(0.f, 0.f, 0.f, 0.f);

    int r_n = 0; float w_n = 0.f;
    if (s < e) { r_n = __ldg(g_esrc + s); w_n = __ldg(g_ew + s); }
    for (int p = s; p < e; p++) {
        int r = r_n; float w = w_n;
        if (p + 1 < e) { r_n = __ldg(g_esrc + p + 1); w_n = __ldg(g_ew + p + 1); }
        const __half* kv = g_KVh + (size_t)r * 128;
        if (lane < 8) {
            float4 kvv = __ldg((const float4*)(Kc + r * 64 + half * 32) + lane);
            ack.x = fmaf(kvv.x, w, ack.x);
            ack.y = fmaf(kvv.y, w, ack.y);
            ack.z = fmaf(kvv.z, w, ack.z);
            ack.w = fmaf(kvv.w, w, ack.w);
        }
#pragma unroll
        for (int u = 0; u < 2; u++) {
            int gh = 2 * half + u;
            float kf = __half2float(__ldg(kv + gh * 16 + i_idx));
            float wk = w * kf;
            uint4 vv = __ldg((const uint4*)(kv + 64 + gh * 16 + jb));  // 8 halfs
            const __half2* hv = (const __half2*)&vv;
#pragma unroll
            for (int c2 = 0; c2 < 4; c2++) {
                float2 f = __half22float2(hv[c2]);
                acc[u][2 * c2]     = fmaf(f.x, wk, acc[u][2 * c2]);
                acc[u][2 * c2 + 1] = fmaf(f.y, wk, acc[u][2 * c2 + 1]);
            }
        }
    }

    // write M1 (fp16) and Kf1 (fp32)
    {
        uint4* dst = (uint4*)g_Mh[1] + (size_t)node * 128 + 64 * half + lane;
#pragma unroll
        for (int u = 0; u < 2; u++) {
            uint4 o;
            __half2* ho = (__half2*)&o;
#pragma unroll
            for (int c2 = 0; c2 < 4; c2++)
                ho[c2] = __floats2half2_rn(acc[u][2 * c2], acc[u][2 * c2 + 1]);
            dst[32 * u] = o;
        }
        if (lane < 8) ((float4*)(g_Kp[1] + node * 64 + half * 32))[lane] = ack;
    }

    // ---- C on lanes 0..7 ----
    const float* Q = g_Q + node * 64;
    float cpart = 0.f;
    if (lane < 8) {
        float4 qc = __ldg((const float4*)(Q + half * 32) + lane);
        cpart = qc.x * ack.x + qc.y * ack.y + qc.z * ack.z + qc.w * ack.w;
    }
    cpart += __shfl_xor_sync(0xFFFFFFFFu, cpart, 1);
    cpart += __shfl_xor_sync(0xFFFFFFFFu, cpart, 2);

    // ---- H reduction over i ----
    float hp[2][8];
    {
#pragma unroll
        for (int u = 0; u < 2; u++) {
            float qh = __ldg(Q + (2 * half + u) * 16 + i_idx);
#pragma unroll
            for (int c = 0; c < 8; c++) hp[u][c] = qh * acc[u][c];
        }
    }
#pragma unroll
    for (int m = 2; m <= 16; m <<= 1) {
#pragma unroll
        for (int u = 0; u < 2; u++)
#pragma unroll
            for (int c = 0; c < 8; c++)
                hp[u][c] += __shfl_xor_sync(0xFFFFFFFFu, hp[u][c], m);
    }

    const int hop = 0;
    float hw0 = __ldg(headwise + 0 * KHOP + hop);
    float hw1 = __ldg(headwise + 1 * KHOP + hop);
    float hw2 = __ldg(headwise + 2 * KHOP + hop);
    float hw3 = __ldg(headwise + 3 * KHOP + hop);
    float mx = fmaxf(fmaxf(hw0, hw1), fmaxf(hw2, hw3));
    float e0 = expf(hw0 - mx), e1 = expf(hw1 - mx), e2 = expf(hw2 - mx), e3 = expf(hw3 - mx);
    float ssum = e0 + e1 + e2 + e3;
    float hopw = __ldg(hopwise + hop + 1);

    float Csel = __shfl_sync(0xFFFFFFFFu, cpart, ((lane >> 1) & 1) * 4) + 1e-5f;

    if (lane < 4) {
        int lh = lane >> 1;
        int gh = 2 * half + lh;
        int jb2 = (lane & 1) * 8;
        float eh = (gh == 0) ? e0 : (gh == 1) ? e1 : (gh == 2) ? e2 : e3;
        float scale = hopw * (eh / ssum) / Csel;
        float hv[8];
#pragma unroll
        for (int c = 0; c < 8; c++) hv[c] = (lh == 0) ? hp[0][c] : hp[1][c];
        float* hd = g_hidden + node * 64 + gh * 16 + jb2;
        float4 a = *(float4*)hd;
        float4 b = *(float4*)(hd + 4);
        a.x += scale * hv[0]; a.y += scale * hv[1]; a.z += scale * hv[2]; a.w += scale * hv[3];
        b.x += scale * hv[4]; b.y += scale * hv[5]; b.z += scale * hv[6]; b.w += scale * hv[7];
        *(float4*)hd = a;
        *(float4*)(hd + 4) = b;
    }
}

// ---------------- hops 1..2: M-gather propagation + H/C + hidden update ----------------
__global__ void __launch_bounds__(256)
k_prop(int cur, int hop, int last,
       const float* __restrict__ hopwise, const float* __restrict__ headwise) {
    int warp = (blockIdx.x * 256 + threadIdx.x) >> 5;
    int node = warp >> 1;
    int half = warp & 1;
    int lane = threadIdx.x & 31;
    if (node >= NN) return;
    int s = g_rowptr[node], e = g_rowptr[node + 1];
    const uint4* Mc = (const uint4*)g_Mh[cur];
    const float* Kc = g_Kp[cur];

    float acc[2][8];
#pragma unroll
    for (int u = 0; u < 2; u++)
#pragma unroll
        for (int c = 0; c < 8; c++) acc[u][c] = 0.f;
    float4 ack = make_float4(0.f, 0.f, 0.f, 0.f);

    int r_n = 0; float w_n = 0.f;
    if (s < e) { r_n = __ldg(g_esrc + s); w_n = __ldg(g_ew + s); }
    for (int p = s; p < e; p++) {
        int r = r_n; float w = w_n;
        if (p + 1 < e) { r_n = __ldg(g_esrc + p + 1); w_n = __ldg(g_ew + p + 1); }
        const uint4* src = Mc + (size_t)r * 128 + 64 * half + lane;
        uint4 v0 = __ldg(src);
        uint4 v1 = __ldg(src + 32);
        if (lane < 8) {
            float4 kv = __ldg((const float4*)(Kc + r * 64 + half * 32) + lane);
            ack.x = fmaf(kv.x, w, ack.x);
            ack.y = fmaf(kv.y, w, ack.y);
            ack.z = fmaf(kv.z, w, ack.z);
            ack.w = fmaf(kv.w, w, ack.w);
        }
        {
            const __half2* hv = (const __half2*)&v0;
#pragma unroll
            for (int c2 = 0; c2 < 4; c2++) {
                float2 f = __half22float2(hv[c2]);
                acc[0][2 * c2]     = fmaf(f.x, w, acc[0][2 * c2]);
                acc[0][2 * c2 + 1] = fmaf(f.y, w, acc[0][2 * c2 + 1]);
            }
        }
        {
            const __half2* hv = (const __half2*)&v1;
#pragma unroll
            for (int c2 = 0; c2 < 4; c2++) {
                float2 f = __half22float2(hv[c2]);
                acc[1][2 * c2]     = fmaf(f.x, w, acc[1][2 * c2]);
                acc[1][2 * c2 + 1] = fmaf(f.y, w, acc[1][2 * c2 + 1]);
            }
        }
    }

    if (!last) {
        uint4* dst = (uint4*)g_Mh[cur ^ 1] + (size_t)node * 128 + 64 * half + lane;
#pragma unroll
        for (int u = 0; u < 2; u++) {
            uint4 o;
            __half2* ho = (__half2*)&o;
#pragma unroll
            for (int c2 = 0; c2 < 4; c2++)
                ho[c2] = __floats2half2_rn(acc[u][2 * c2], acc[u][2 * c2 + 1]);
            dst[32 * u] = o;
        }
        if (lane < 8) ((float4*)(g_Kp[cur ^ 1] + node * 64 + half * 32))[lane] = ack;
    }

    const float* Q = g_Q + node * 64;
    float cpart = 0.f;
    if (lane < 8) {
        float4 qc = __ldg((const float4*)(Q + half * 32) + lane);
        cpart = qc.x * ack.x + qc.y * ack.y + qc.z * ack.z + qc.w * ack.w;
    }
    cpart += __shfl_xor_sync(0xFFFFFFFFu, cpart, 1);
    cpart += __shfl_xor_sync(0xFFFFFFFFu, cpart, 2);

    float hp[2][8];
    {
        int i = lane >> 1;
#pragma unroll
        for (int u = 0; u < 2; u++) {
            float qh = __ldg(Q + (2 * half + u) * 16 + i);
#pragma unroll
            for (int c = 0; c < 8; c++) hp[u][c] = qh * acc[u][c];
        }
    }
#pragma unroll
    for (int m = 2; m <= 16; m <<= 1) {
#pragma unroll
        for (int u = 0; u < 2; u++)
#pragma unroll
            for (int c = 0; c < 8; c++)
                hp[u][c] += __shfl_xor_sync(0xFFFFFFFFu, hp[u][c], m);
    }

    float hw0 = __ldg(headwise + 0 * KHOP + hop);
    float hw1 = __ldg(headwise + 1 * KHOP + hop);
    float hw2 = __ldg(headwise + 2 * KHOP + hop);
    float hw3 = __ldg(headwise + 3 * KHOP + hop);
    float mx = fmaxf(fmaxf(hw0, hw1), fmaxf(hw2, hw3));
    float e0 = expf(hw0 - mx), e1 = expf(hw1 - mx), e2 = expf(hw2 - mx), e3 = expf(hw3 - mx);
    float ssum = e0 + e1 + e2 + e3;
    float hopw = __ldg(hopwise + hop + 1);

    float Csel = __shfl_sync(0xFFFFFFFFu, cpart, ((lane >> 1) & 1) * 4) + 1e-5f;

    if (lane < 4) {
        int lh = lane >> 1;
        int gh = 2 * half + lh;
        int jb = (lane & 1) * 8;
        float eh = (gh == 0) ? e0 : (gh == 1) ? e1 : (gh == 2) ? e2 : e3;
        float scale = hopw * (eh / ssum) / Csel;
        float hv[8];
#pragma unroll
        for (int c = 0; c < 8; c++) hv[c] = (lh == 0) ? hp[0][c] : hp[1][c];
        float* hd = g_hidden + node * 64 + gh * 16 + jb;
        float4 a = *(float4*)hd;
        float4 b = *(float4*)(hd + 4);
        a.x += scale * hv[0]; a.y += scale * hv[1]; a.z += scale * hv[2]; a.w += scale * hv[3];
        b.x += scale * hv[4]; b.y += scale * hv[5]; b.z += scale * hv[6]; b.w += scale * hv[7];
        *(float4*)hd = a;
        *(float4*)(hd + 4) = b;
    }
}

// ---------------- output projection: hidden[N,64] @ Wo[64,16] + bo ----------------
__global__ void k_proj(const float* __restrict__ Wo, const float* __restrict__ bo,
                       float* __restrict__ outHid) {
    int idx = blockIdx.x * blockDim.x + threadIdx.x;
    if (idx >= NN * 16) return;
    int n = idx >> 4, j = idx & 15;
    float acc = __ldg(bo + j);
    const float* hd = g_hidden + n * 64;
#pragma unroll
    for (int k = 0; k < 64; k++) acc = fmaf(hd[k], __ldg(Wo + k * 16 + j), acc);
    outHid[idx] = acc;
}

// ---------------- edge regression head ----------------
__global__ void k_edge(const int* __restrict__ fsrc, const int* __restrict__ fdst,
                       const float* __restrict__ hid,
                       const float* __restrict__ Wf1, const float* __restrict__ bf1,
                       const float* __restrict__ Wf2, const float* __restrict__ bf2,
                       float* __restrict__ out) {
    __shared__ float sW1[512];
    __shared__ float sb1[16];
    __shared__ float sW2[16];
    __shared__ float sb2;
    int t = threadIdx.x;
    sW1[t] = __ldg(Wf1 + t);
    sW1[t + 256] = __ldg(Wf1 + t + 256);
    if (t < 16) { sb1[t] = __ldg(bf1 + t); sW2[t] = __ldg(Wf2 + t); }
    if (t == 0) sb2 = __ldg(bf2);
    __syncthreads();
    int idx = blockIdx.x * blockDim.x + t;
    if (idx >= FEE) return;
    int s = fsrc[idx], d = fdst[idx];
    float he[32];
    {
        const float4* ps = (const float4*)(hid + s * 16);
        const float4* pd = (const float4*)(hid + d * 16);
#pragma unroll
        for (int u = 0; u < 4; u++) {
            float4 a = __ldg(ps + u);
            he[4 * u + 0] = a.x; he[4 * u + 1] = a.y; he[4 * u + 2] = a.z; he[4 * u + 3] = a.w;
            float4 b = __ldg(pd + u);
            he[16 + 4 * u + 0] = b.x; he[16 + 4 * u + 1] = b.y; he[16 + 4 * u + 2] = b.z; he[16 + 4 * u + 3] = b.w;
        }
    }
    float o = sb2;
#pragma unroll
    for (int j = 0; j < 16; j++) {
        float a = sb1[j];
#pragma unroll
        for (int k = 0; k < 32; k++) a = fmaf(he[k], sW1[k * 16 + j], a);
        a = a / (1.0f + expf(-a));  // silu
        o = fmaf(a, sW2[j], o);
    }
    out[idx] = o;
}

// ---------------- launch ----------------
extern "C" void kernel_launch(void* const* d_in, const int* in_sizes, int n_in,
                              void* d_out, int out_size) {
    (void)in_sizes; (void)n_in; (void)out_size;
    const float* x      = (const float*)d_in[0];
    const int*   ei     = (const int*)d_in[1];
    const int*   fei    = (const int*)d_in[2];
    const int*   tsteps = (const int*)d_in[3];
    const float* Wi  = (const float*)d_in[4];
    const float* bi  = (const float*)d_in[5];
    const float* Wt1 = (const float*)d_in[6];
    const float* bt1 = (const float*)d_in[7];
    const float* Wt2 = (const float*)d_in[8];
    const float* bt2 = (const float*)d_in[9];
    const float* WQ  = (const float*)d_in[10];
    const float* bQ  = (const float*)d_in[11];
    const float* WK  = (const float*)d_in[12];
    const float* bK  = (const float*)d_in[13];
    const float* WV  = (const float*)d_in[14];
    const float* bV  = (const float*)d_in[15];
    const float* Wo  = (const float*)d_in[16];
    const float* bo  = (const float*)d_in[17];
    const float* hopwise  = (const float*)d_in[18];
    const float* headwise = (const float*)d_in[19];
    const float* Wf1 = (const float*)d_in[20];
    const float* bf1 = (const float*)d_in[21];
    const float* Wf2 = (const float*)d_in[22];
    const float* bf2 = (const float*)d_in[23];

    float* out = (float*)d_out;
    float* outHid = out + FEE;

    const int* row = ei;
    const int* col = ei + EE;
    const int* fsrc = fei;
    const int* fdst = fei + FEE;

    k_temb<<<128, 64>>>(Wt1, bt1, Wt2, bt2);
    k_init<<<(NN + 255) / 256, 256>>>();
    k_hist<<<(EE + 255) / 256, 256>>>(col);
    k_scanA<<<79, 256>>>();
    k_scanB<<<1, 128>>>();
    k_scanC<<<79, 256>>>();
    k_fill<<<(EE + 255) / 256, 256>>>(row, col);

    cudaFuncSetAttribute(k_node, cudaFuncAttributeMaxDynamicSharedMemorySize, 49152);
    k_node<<<(NN + 63) / 64, 256, 49152>>>(x, tsteps, Wi, bi,
                                           WQ, bQ, WK, bK, WV, bV, hopwise);

    // hop 0: rank-1 gather (writes M1 -> g_Mh[1], Kf1 -> g_Kp[1])
    k_prop1<<<(NN * 64 + 255) / 256, 256>>>(hopwise, headwise);
    // hop 1: M gather (reads [1], writes [0])
    k_prop<<<(NN * 64 + 255) / 256, 256>>>(1, 1, 0, hopwise, headwise);
    // hop 2: M gather, last (reads [0], no writes)
    k_prop<<<(NN * 64 + 255) / 256, 256>>>(0, 2, 1, hopwise, headwise);

    k_proj<<<(NN * 16 + 255) / 256, 256>>>(Wo, bo, outHid);
    k_edge<<<(FEE + 255) / 256, 256>>>(fsrc, fdst, outHid, Wf1, bf1, Wf2, bf2, out);
}

// round 8
// speedup vs baseline: 1.3519x; 1.3519x over previous
#include <cuda_runtime.h>
#include <cuda_fp16.h>
#include <math.h>

#define NN   20000
#define EE   160000
#define FEE  500000
#define KHOP 3

// ---------------- scratch (static __device__, no allocations) ----------------
__device__ int     g_degi[NN];
__device__ int     g_cnt[NN];
__device__ float   g_deginv[NN];
__device__ int     g_rowptr[NN + 1];
__device__ int     g_bsum[96];
__device__ int     g_esrc[EE];
__device__ float   g_ew[EE];
__device__ float   g_temb[128 * 64];
__device__ float   g_Q[NN * 64];
__device__ float   g_Kp[2][NN * 64];
__device__ __half2 g_Mh[2][(size_t)NN * 512];   // M in fp16, 512 half2 per node
__device__ float   g_hidden[NN * 64];

// ---------------- timestep-embedding table (128 distinct timesteps) ----------------
__global__ void __launch_bounds__(64)
k_temb(const float* __restrict__ Wt1, const float* __restrict__ bt1,
       const float* __restrict__ Wt2, const float* __restrict__ bt2) {
    __shared__ float se[64];
    __shared__ float s1[256];
    int ts = blockIdx.x;      // 0..127
    int j = threadIdx.x;      // 0..63
    float tsf = (float)ts * 31.25f;   // 4000/128
    {
        const float negLn = -logf(10000.0f) / 31.0f;
        int f = j & 31;
        float arg = tsf * expf(negLn * (float)f);
        se[j] = (j < 32) ? sinf(arg) : cosf(arg);
    }
    __syncthreads();
    for (int c = j; c < 256; c += 64) {
        float a = __ldg(bt1 + c);
        for (int k = 0; k < 64; k++) a = fmaf(se[k], __ldg(Wt1 + k * 256 + c), a);
        s1[c] = a / (1.0f + expf(-a));   // silu
    }
    __syncthreads();
    {
        float a = __ldg(bt2 + j);
        for (int k = 0; k < 256; k++) a = fmaf(s1[k], __ldg(Wt2 + k * 64 + j), a);
        g_temb[ts * 64 + j] = a;
    }
}

// ---------------- CSR build ----------------
__global__ void k_init() {
    int i = blockIdx.x * blockDim.x + threadIdx.x;
    if (i < NN) { g_degi[i] = 0; g_cnt[i] = 0; }
}

__global__ void k_hist(const int* __restrict__ col) {
    int e = blockIdx.x * blockDim.x + threadIdx.x;
    if (e < EE) atomicAdd(&g_degi[col[e]], 1);
}

// 79 blocks x 256: per-block exclusive scan -> g_rowptr (local), block totals -> g_bsum
__global__ void __launch_bounds__(256) k_scanA() {
    __shared__ int wsum[8];
    int t = threadIdx.x, b = blockIdx.x;
    int idx = b * 256 + t;
    int d = (idx < NN) ? g_degi[idx] : 0;
    int lane = t & 31, w = t >> 5;
    int v = d;
#pragma unroll
    for (int m = 1; m < 32; m <<= 1) {
        int o = __shfl_up_sync(0xFFFFFFFFu, v, m);
        if (lane >= m) v += o;
    }
    if (lane == 31) wsum[w] = v;
    __syncthreads();
    if (t == 0) {
        int run = 0;
#pragma unroll
        for (int i = 0; i < 8; i++) { int xx = wsum[i]; wsum[i] = run; run += xx; }
        g_bsum[b] = run;
    }
    __syncthreads();
    if (idx < NN) g_rowptr[idx] = v - d + wsum[w];
}

// 1 block x 128: exclusive scan of 79 block sums in place
__global__ void __launch_bounds__(128) k_scanB() {
    __shared__ int ws[4];
    int t = threadIdx.x;
    int v0 = (t < 79) ? g_bsum[t] : 0;
    int v = v0;
    int lane = t & 31, w = t >> 5;
#pragma unroll
    for (int m = 1; m < 32; m <<= 1) {
        int o = __shfl_up_sync(0xFFFFFFFFu, v, m);
        if (lane >= m) v += o;
    }
    if (lane == 31) ws[w] = v;
    __syncthreads();
    if (t == 0) {
        int run = 0;
#pragma unroll
        for (int i = 0; i < 4; i++) { int xx = ws[i]; ws[i] = run; run += xx; }
    }
    __syncthreads();
    if (t < 79) g_bsum[t] = v - v0 + ws[w];
}

// 79 blocks x 256: add block offsets, compute deginv, close rowptr
__global__ void __launch_bounds__(256) k_scanC() {
    int idx = blockIdx.x * 256 + threadIdx.x;
    if (idx < NN) {
        g_rowptr[idx] += g_bsum[blockIdx.x];
        int dg = g_degi[idx];
        g_deginv[idx] = dg > 0 ? 1.0f / (float)dg : 0.0f;
    }
    if (idx == 0) g_rowptr[NN] = EE;
}

__global__ void k_fill(const int* __restrict__ row, const int* __restrict__ col) {
    int e = blockIdx.x * blockDim.x + threadIdx.x;
    if (e < EE) {
        int c = col[e];
        int r = row[e];
        int p = atomicAdd(&g_cnt[c], 1);
        int pos = g_rowptr[c] + p;
        g_esrc[pos] = r;
        g_ew[pos] = g_deginv[r];   // norm = deg_inv[source]; deg over destinations
    }
}

// ---------------- fused node-feature pipeline ----------------
// block = 256 threads handles 64 nodes. Dynamic smem: sX[64*128] | sB[64*192]
__global__ void __launch_bounds__(256)
k_node(const float* __restrict__ x, const int* __restrict__ tsteps,
       const float* __restrict__ Wi, const float* __restrict__ bi,
       const float* __restrict__ WQ, const float* __restrict__ bQ,
       const float* __restrict__ WK, const float* __restrict__ bK,
       const float* __restrict__ WV, const float* __restrict__ bV,
       const float* __restrict__ hopwise) {
    extern __shared__ float sm[];
    float* sX = sm;               // 8192 floats
    float* sB = sm + 64 * 128;    // 12288 floats: h | K | V
    const int t = threadIdx.x;
    const int nb = blockIdx.x * 64;
    const int lane = t & 31, wid = t >> 5;

    // ---- load x tile (float4, coalesced) ----
    {
        const float4* xv = (const float4*)x;
        float4* sxv = (float4*)sX;
#pragma unroll
        for (int i = 0; i < 8; i++) {
            int idx = t + 256 * i;      // float4 index in tile (2048 total)
            int n = idx >> 5;           // 32 float4 per row
            int c4 = idx & 31;
            float4 v = make_float4(0.f, 0.f, 0.f, 0.f);
            if (nb + n < NN) v = __ldg(xv + (size_t)(nb + n) * 32 + c4);
            sxv[idx] = v;
        }
    }
    __syncthreads();

    // ---- h = relu(sX @ Wi + bi + temb[ts]) -> sB[0:4096] ----
    {
        float acc[8][2];
        {
            float2 b = __ldg((const float2*)bi + lane);
#pragma unroll
            for (int i = 0; i < 8; i++) { acc[i][0] = b.x; acc[i][1] = b.y; }
        }
        for (int k0 = 0; k0 < 128; k0 += 4) {
            float wv[4][2];
#pragma unroll
            for (int r = 0; r < 4; r++) {
                float2 w = __ldg((const float2*)(Wi + (k0 + r) * 64) + lane);
                wv[r][0] = w.x; wv[r][1] = w.y;
            }
#pragma unroll
            for (int i = 0; i < 8; i++) {
                float4 a = *(const float4*)(sX + (wid + 8 * i) * 128 + k0);
#pragma unroll
                for (int c = 0; c < 2; c++) {
                    acc[i][c] = fmaf(a.x, wv[0][c],
                                fmaf(a.y, wv[1][c],
                                fmaf(a.z, wv[2][c],
                                fmaf(a.w, wv[3][c], acc[i][c]))));
                }
            }
        }
#pragma unroll
        for (int i = 0; i < 8; i++) {
            int rowl = wid + 8 * i;
            int g = nb + rowl;
            int ts = (g < NN) ? __ldg(tsteps + g) : 0;
            const float2* te = (const float2*)(g_temb + ts * 64) + lane;
            float2 tv = *te;
#pragma unroll
            for (int c = 0; c < 2; c++) {
                float v = acc[i][c] + ((c == 0) ? tv.x : tv.y);
                v = fmaxf(v, 0.0f);
                sB[rowl * 64 + lane * 2 + c] = v;
            }
        }
    }
    __syncthreads();

    // ---- Q,K,V from h ----
    {
        float aq[8][2], ak[8][2], av[8][2];
        {
            float2 bq = __ldg((const float2*)bQ + lane);
            float2 bk = __ldg((const float2*)bK + lane);
            float2 bv = __ldg((const float2*)bV + lane);
#pragma unroll
            for (int i = 0; i < 8; i++) {
                aq[i][0] = bq.x; aq[i][1] = bq.y;
                ak[i][0] = bk.x; ak[i][1] = bk.y;
                av[i][0] = bv.x; av[i][1] = bv.y;
            }
        }
        for (int k0 = 0; k0 < 64; k0 += 4) {
            float wq[4][2], wk[4][2], wvv[4][2];
#pragma unroll
            for (int r = 0; r < 4; r++) {
                float2 a1 = __ldg((const float2*)(WQ + (k0 + r) * 64) + lane);
                float2 a2 = __ldg((const float2*)(WK + (k0 + r) * 64) + lane);
                float2 a3 = __ldg((const float2*)(WV + (k0 + r) * 64) + lane);
                wq[r][0] = a1.x; wq[r][1] = a1.y;
                wk[r][0] = a2.x; wk[r][1] = a2.y;
                wvv[r][0] = a3.x; wvv[r][1] = a3.y;
            }
#pragma unroll
            for (int i = 0; i < 8; i++) {
                float4 a = *(const float4*)(sB + (wid + 8 * i) * 64 + k0);
#pragma unroll
                for (int c = 0; c < 2; c++) {
                    aq[i][c] = fmaf(a.x, wq[0][c], fmaf(a.y, wq[1][c], fmaf(a.z, wq[2][c], fmaf(a.w, wq[3][c], aq[i][c]))));
                    ak[i][c] = fmaf(a.x, wk[0][c], fmaf(a.y, wk[1][c], fmaf(a.z, wk[2][c], fmaf(a.w, wk[3][c], ak[i][c]))));
                    av[i][c] = fmaf(a.x, wvv[0][c], fmaf(a.y, wvv[1][c], fmaf(a.z, wvv[2][c], fmaf(a.w, wvv[3][c], av[i][c]))));
                }
            }
        }
        __syncthreads();
        float hop0 = __ldg(hopwise);
#pragma unroll
        for (int i = 0; i < 8; i++) {
            int nl = wid + 8 * i;
            int g = nb + nl;
#pragma unroll
            for (int c = 0; c < 2; c++) {
                int cc = lane * 2 + c;
                float q = aq[i][c]; q = (q > 0.f) ? q + 1.f : expf(q);
                float kk = ak[i][c]; kk = (kk > 0.f) ? kk + 1.f : expf(kk);
                float vv = av[i][c];
                sB[4096 + nl * 64 + cc] = kk;
                sB[8192 + nl * 64 + cc] = vv;
                if (g < NN) {
                    g_Q[g * 64 + cc] = q;
                    g_Kp[0][g * 64 + cc] = kk;
                    g_hidden[g * 64 + cc] = vv * hop0;
                }
            }
        }
    }
    __syncthreads();

    // ---- M0[n,h,i,j] = K[n,h,i] * V[n,h,j], stored as half2 ----
    {
        const float* sK = sB + 4096;
        const float* sV = sB + 8192;
        for (int idx = t; idx < 64 * 512; idx += 256) {
            int n = idx >> 9;
            int r2 = idx & 511;           // half2 index within node
            int h = r2 >> 7;
            int rem = r2 & 127;
            int i = rem >> 3;
            int j2 = (rem & 7) * 2;
            int g = nb + n;
            if (g < NN) {
                float kk = sK[n * 64 + h * 16 + i];
                float v0 = sV[n * 64 + h * 16 + j2];
                float v1 = sV[n * 64 + h * 16 + j2 + 1];
                g_Mh[0][(size_t)g * 512 + r2] = __floats2half2_rn(kk * v0, kk * v1);
            }
        }
    }
}

// ---------------- fused propagation + H/C + hidden update ----------------
// TWO warps per destination node; warp `half` owns heads {2*half, 2*half+1}
// (M vec indices lane + 32*(2*half+uu), uu in {0,1}).
__global__ void __launch_bounds__(256)
k_prop(int cur, int hop, int last,
       const float* __restrict__ hopwise, const float* __restrict__ headwise) {
    int warp = (blockIdx.x * 256 + threadIdx.x) >> 5;
    int node = warp >> 1;
    int half = warp & 1;
    int lane = threadIdx.x & 31;
    if (node >= NN) return;
    int s = g_rowptr[node], e = g_rowptr[node + 1];
    const uint4* Mc = (const uint4*)g_Mh[cur];
    const float* Kc = g_Kp[cur];

    float acc[2][8];
#pragma unroll
    for (int u = 0; u < 2; u++)
#pragma unroll
        for (int c = 0; c < 8; c++) acc[u][c] = 0.f;
    float4 ack = make_float4(0.f, 0.f, 0.f, 0.f);

    // software-pipelined edge loop: (index, weight) prefetched one edge ahead
    int r_n = 0; float w_n = 0.f;
    if (s < e) { r_n = __ldg(g_esrc + s); w_n = __ldg(g_ew + s); }
    for (int p = s; p < e; p++) {
        int r = r_n; float w = w_n;
        if (p + 1 < e) { r_n = __ldg(g_esrc + p + 1); w_n = __ldg(g_ew + p + 1); }
        const uint4* src = Mc + (size_t)r * 128 + 64 * half + lane;
        uint4 v0 = __ldg(src);
        uint4 v1 = __ldg(src + 32);
        if (lane < 8) {
            float4 kv = __ldg((const float4*)(Kc + r * 64 + half * 32) + lane);
            ack.x = fmaf(kv.x, w, ack.x);
            ack.y = fmaf(kv.y, w, ack.y);
            ack.z = fmaf(kv.z, w, ack.z);
            ack.w = fmaf(kv.w, w, ack.w);
        }
        {
            const __half2* hv = (const __half2*)&v0;
#pragma unroll
            for (int c2 = 0; c2 < 4; c2++) {
                float2 f = __half22float2(hv[c2]);
                acc[0][2 * c2]     = fmaf(f.x, w, acc[0][2 * c2]);
                acc[0][2 * c2 + 1] = fmaf(f.y, w, acc[0][2 * c2 + 1]);
            }
        }
        {
            const __half2* hv = (const __half2*)&v1;
#pragma unroll
            for (int c2 = 0; c2 < 4; c2++) {
                float2 f = __half22float2(hv[c2]);
                acc[1][2 * c2]     = fmaf(f.x, w, acc[1][2 * c2]);
                acc[1][2 * c2 + 1] = fmaf(f.y, w, acc[1][2 * c2 + 1]);
            }
        }
    }

    // write propagated M/Kf (skip on last hop — nobody consumes them)
    if (!last) {
        uint4* dst = (uint4*)g_Mh[cur ^ 1] + (size_t)node * 128 + 64 * half + lane;
#pragma unroll
        for (int u = 0; u < 2; u++) {
            uint4 o;
            __half2* ho = (__half2*)&o;
#pragma unroll
            for (int c2 = 0; c2 < 4; c2++)
                ho[c2] = __floats2half2_rn(acc[u][2 * c2], acc[u][2 * c2 + 1]);
            dst[32 * u] = o;
        }
        if (lane < 8) ((float4*)(g_Kp[cur ^ 1] + node * 64 + half * 32))[lane] = ack;
    }

    // ---- C[h] = Q[h,:].Kf[h,:] on lanes 0..7 (local head = lane>>2) ----
    const float* Q = g_Q + node * 64;
    float cpart = 0.f;
    if (lane < 8) {
        float4 qc = __ldg((const float4*)(Q + half * 32) + lane);
        cpart = qc.x * ack.x + qc.y * ack.y + qc.z * ack.z + qc.w * ack.w;
    }
    cpart += __shfl_xor_sync(0xFFFFFFFFu, cpart, 1);
    cpart += __shfl_xor_sync(0xFFFFFFFFu, cpart, 2);
    // lanes 0-3 hold C[local 0], lanes 4-7 hold C[local 1]

    // ---- H[u][j] = sum_i Q[gh,i]*M[gh,i,j]; i = lane>>1, j = 8*(lane&1)+c ----
    float hp[2][8];
    {
        int i = lane >> 1;
#pragma unroll
        for (int u = 0; u < 2; u++) {
            float qh = __ldg(Q + (2 * half + u) * 16 + i);
#pragma unroll
            for (int c = 0; c < 8; c++) hp[u][c] = qh * acc[u][c];
        }
    }
#pragma unroll
    for (int m = 2; m <= 16; m <<= 1) {
#pragma unroll
        for (int u = 0; u < 2; u++)
#pragma unroll
            for (int c = 0; c < 8; c++)
                hp[u][c] += __shfl_xor_sync(0xFFFFFFFFu, hp[u][c], m);
    }

    // gamma[h] = hopwise[hop+1] * softmax_over_heads(headwise[:,hop])[h]
    float hw0 = __ldg(headwise + 0 * KHOP + hop);
    float hw1 = __ldg(headwise + 1 * KHOP + hop);
    float hw2 = __ldg(headwise + 2 * KHOP + hop);
    float hw3 = __ldg(headwise + 3 * KHOP + hop);
    float mx = fmaxf(fmaxf(hw0, hw1), fmaxf(hw2, hw3));
    float e0 = expf(hw0 - mx), e1 = expf(hw1 - mx), e2 = expf(hw2 - mx), e3 = expf(hw3 - mx);
    float ssum = e0 + e1 + e2 + e3;
    float hopw = __ldg(hopwise + hop + 1);

    float Csel = __shfl_sync(0xFFFFFFFFu, cpart, ((lane >> 1) & 1) * 4) + 1e-5f;

    if (lane < 4) {
        int lh = lane >> 1;            // local head
        int gh = 2 * half + lh;        // global head
        int jb = (lane & 1) * 8;
        float eh = (gh == 0) ? e0 : (gh == 1) ? e1 : (gh == 2) ? e2 : e3;
        float scale = hopw * (eh / ssum) / Csel;
        float hv[8];
#pragma unroll
        for (int c = 0; c < 8; c++) hv[c] = (lh == 0) ? hp[0][c] : hp[1][c];
        float* hd = g_hidden + node * 64 + gh * 16 + jb;
        float4 a = *(float4*)hd;
        float4 b = *(float4*)(hd + 4);
        a.x += scale * hv[0]; a.y += scale * hv[1]; a.z += scale * hv[2]; a.w += scale * hv[3];
        b.x += scale * hv[4]; b.y += scale * hv[5]; b.z += scale * hv[6]; b.w += scale * hv[7];
        *(float4*)hd = a;
        *(float4*)(hd + 4) = b;
    }
}

// ---------------- output projection: hidden[N,64] @ Wo[64,16] + bo ----------------
__global__ void k_proj(const float* __restrict__ Wo, const float* __restrict__ bo,
                       float* __restrict__ outHid) {
    int idx = blockIdx.x * blockDim.x + threadIdx.x;
    if (idx >= NN * 16) return;
    int n = idx >> 4, j = idx & 15;
    float acc = __ldg(bo + j);
    const float* hd = g_hidden + n * 64;
#pragma unroll
    for (int k = 0; k < 64; k++) acc = fmaf(hd[k], __ldg(Wo + k * 16 + j), acc);
    outHid[idx] = acc;
}

// ---------------- edge regression head ----------------
__global__ void k_edge(const int* __restrict__ fsrc, const int* __restrict__ fdst,
                       const float* __restrict__ hid,
                       const float* __restrict__ Wf1, const float* __restrict__ bf1,
                       const float* __restrict__ Wf2, const float* __restrict__ bf2,
                       float* __restrict__ out) {
    __shared__ float sW1[512];
    __shared__ float sb1[16];
    __shared__ float sW2[16];
    __shared__ float sb2;
    int t = threadIdx.x;
    sW1[t] = __ldg(Wf1 + t);
    sW1[t + 256] = __ldg(Wf1 + t + 256);
    if (t < 16) { sb1[t] = __ldg(bf1 + t); sW2[t] = __ldg(Wf2 + t); }
    if (t == 0) sb2 = __ldg(bf2);
    __syncthreads();
    int idx = blockIdx.x * blockDim.x + t;
    if (idx >= FEE) return;
    int s = fsrc[idx], d = fdst[idx];
    float he[32];
    {
        const float4* ps = (const float4*)(hid + s * 16);
        const float4* pd = (const float4*)(hid + d * 16);
#pragma unroll
        for (int u = 0; u < 4; u++) {
            float4 a = __ldg(ps + u);
            he[4 * u + 0] = a.x; he[4 * u + 1] = a.y; he[4 * u + 2] = a.z; he[4 * u + 3] = a.w;
            float4 b = __ldg(pd + u);
            he[16 + 4 * u + 0] = b.x; he[16 + 4 * u + 1] = b.y; he[16 + 4 * u + 2] = b.z; he[16 + 4 * u + 3] = b.w;
        }
    }
    float o = sb2;
#pragma unroll
    for (int j = 0; j < 16; j++) {
        float a = sb1[j];
#pragma unroll
        for (int k = 0; k < 32; k++) a = fmaf(he[k], sW1[k * 16 + j], a);
        a = a / (1.0f + expf(-a));  // silu
        o = fmaf(a, sW2[j], o);
    }
    out[idx] = o;
}

// ---------------- launch ----------------
extern "C" void kernel_launch(void* const* d_in, const int* in_sizes, int n_in,
                              void* d_out, int out_size) {
    (void)in_sizes; (void)n_in; (void)out_size;
    const float* x      = (const float*)d_in[0];
    const int*   ei     = (const int*)d_in[1];
    const int*   fei    = (const int*)d_in[2];
    const int*   tsteps = (const int*)d_in[3];
    const float* Wi  = (const float*)d_in[4];
    const float* bi  = (const float*)d_in[5];
    const float* Wt1 = (const float*)d_in[6];
    const float* bt1 = (const float*)d_in[7];
    const float* Wt2 = (const float*)d_in[8];
    const float* bt2 = (const float*)d_in[9];
    const float* WQ  = (const float*)d_in[10];
    const float* bQ  = (const float*)d_in[11];
    const float* WK  = (const float*)d_in[12];
    const float* bK  = (const float*)d_in[13];
    const float* WV  = (const float*)d_in[14];
    const float* bV  = (const float*)d_in[15];
    const float* Wo  = (const float*)d_in[16];
    const float* bo  = (const float*)d_in[17];
    const float* hopwise  = (const float*)d_in[18];
    const float* headwise = (const float*)d_in[19];
    const float* Wf1 = (const float*)d_in[20];
    const float* bf1 = (const float*)d_in[21];
    const float* Wf2 = (const float*)d_in[22];
    const float* bf2 = (const float*)d_in[23];

    float* out = (float*)d_out;
    float* outHid = out + FEE;

    const int* row = ei;
    const int* col = ei + EE;
    const int* fsrc = fei;
    const int* fdst = fei + FEE;

    k_temb<<<128, 64>>>(Wt1, bt1, Wt2, bt2);
    k_init<<<(NN + 255) / 256, 256>>>();
    k_hist<<<(EE + 255) / 256, 256>>>(col);
    k_scanA<<<79, 256>>>();
    k_scanB<<<1, 128>>>();
    k_scanC<<<79, 256>>>();
    k_fill<<<(EE + 255) / 256, 256>>>(row, col);

    cudaFuncSetAttribute(k_node, cudaFuncAttributeMaxDynamicSharedMemorySize, 81920);
    k_node<<<(NN + 63) / 64, 256, 81920>>>(x, tsteps, Wi, bi,
                                           WQ, bQ, WK, bK, WV, bV, hopwise);

    int cur = 0;
    for (int hop = 0; hop < KHOP; hop++) {
        k_prop<<<(NN * 64 + 255) / 256, 256>>>(cur, hop, hop == KHOP - 1, hopwise, headwise);
        cur ^= 1;
    }

    k_proj<<<(NN * 16 + 255) / 256, 256>>>(Wo, bo, outHid);
    k_edge<<<(FEE + 255) / 256, 256>>>(fsrc, fdst, outHid, Wf1, bf1, Wf2, bf2, out);
}

// round 9
// speedup vs baseline: 1.4498x; 1.0724x over previous
#include <cuda_runtime.h>
#include <cuda_fp16.h>
#include <math.h>

#define NN   20000
#define EE   160000
#define FEE  500000
#define KHOP 3

// ---------------- scratch (static __device__, no allocations) ----------------
__device__ int     g_degi[NN];
__device__ int     g_cnt[NN];
__device__ float   g_deginv[NN];
__device__ int     g_rowptr[NN + 1];
__device__ int     g_bsum[96];
__device__ int     g_esrc[EE];
__device__ float   g_ew[EE];
__device__ float   g_temb[128 * 64];
__device__ float   g_Q[NN * 64];
__device__ float   g_Kp[2][NN * 64];
__device__ __half2 g_Mh[2][(size_t)NN * 512];   // M in fp16, 512 half2 per node
__device__ float   g_hidden[NN * 64];

// ---------------- timestep-embedding table (128 distinct timesteps) ----------------
__global__ void __launch_bounds__(64)
k_temb(const float* __restrict__ Wt1, const float* __restrict__ bt1,
       const float* __restrict__ Wt2, const float* __restrict__ bt2) {
    __shared__ float se[64];
    __shared__ float s1[256];
    int ts = blockIdx.x;      // 0..127
    int j = threadIdx.x;      // 0..63
    float tsf = (float)ts * 31.25f;   // 4000/128
    {
        const float negLn = -logf(10000.0f) / 31.0f;
        int f = j & 31;
        float arg = tsf * expf(negLn * (float)f);
        se[j] = (j < 32) ? sinf(arg) : cosf(arg);
    }
    __syncthreads();
    for (int c = j; c < 256; c += 64) {
        float a = __ldg(bt1 + c);
        for (int k = 0; k < 64; k++) a = fmaf(se[k], __ldg(Wt1 + k * 256 + c), a);
        s1[c] = a / (1.0f + expf(-a));   // silu
    }
    __syncthreads();
    {
        float a = __ldg(bt2 + j);
        for (int k = 0; k < 256; k++) a = fmaf(s1[k], __ldg(Wt2 + k * 64 + j), a);
        g_temb[ts * 64 + j] = a;
    }
}

// ---------------- CSR build ----------------
__global__ void k_init() {
    int i = blockIdx.x * blockDim.x + threadIdx.x;
    if (i < NN) { g_degi[i] = 0; g_cnt[i] = 0; }
}

__global__ void k_hist(const int* __restrict__ col) {
    int e = blockIdx.x * blockDim.x + threadIdx.x;
    if (e < EE) atomicAdd(&g_degi[col[e]], 1);
}

// 79 blocks x 256: per-block exclusive scan -> g_rowptr (local), block totals -> g_bsum
__global__ void __launch_bounds__(256) k_scanA() {
    __shared__ int wsum[8];
    int t = threadIdx.x, b = blockIdx.x;
    int idx = b * 256 + t;
    int d = (idx < NN) ? g_degi[idx] : 0;
    int lane = t & 31, w = t >> 5;
    int v = d;
#pragma unroll
    for (int m = 1; m < 32; m <<= 1) {
        int o = __shfl_up_sync(0xFFFFFFFFu, v, m);
        if (lane >= m) v += o;
    }
    if (lane == 31) wsum[w] = v;
    __syncthreads();
    if (t == 0) {
        int run = 0;
#pragma unroll
        for (int i = 0; i < 8; i++) { int xx = wsum[i]; wsum[i] = run; run += xx; }
        g_bsum[b] = run;
    }
    __syncthreads();
    if (idx < NN) g_rowptr[idx] = v - d + wsum[w];
}

// 1 block x 128: exclusive scan of 79 block sums in place
__global__ void __launch_bounds__(128) k_scanB() {
    __shared__ int ws[4];
    int t = threadIdx.x;
    int v0 = (t < 79) ? g_bsum[t] : 0;
    int v = v0;
    int lane = t & 31, w = t >> 5;
#pragma unroll
    for (int m = 1; m < 32; m <<= 1) {
        int o = __shfl_up_sync(0xFFFFFFFFu, v, m);
        if (lane >= m) v += o;
    }
    if (lane == 31) ws[w] = v;
    __syncthreads();
    if (t == 0) {
        int run = 0;
#pragma unroll
        for (int i = 0; i < 4; i++) { int xx = ws[i]; ws[i] = run; run += xx; }
    }
    __syncthreads();
    if (t < 79) g_bsum[t] = v - v0 + ws[w];
}

// 79 blocks x 256: add block offsets, compute deginv, close rowptr
__global__ void __launch_bounds__(256) k_scanC() {
    int idx = blockIdx.x * 256 + threadIdx.x;
    if (idx < NN) {
        g_rowptr[idx] += g_bsum[blockIdx.x];
        int dg = g_degi[idx];
        g_deginv[idx] = dg > 0 ? 1.0f / (float)dg : 0.0f;
    }
    if (idx == 0) g_rowptr[NN] = EE;
}

__global__ void k_fill(const int* __restrict__ row, const int* __restrict__ col) {
    int e = blockIdx.x * blockDim.x + threadIdx.x;
    if (e < EE) {
        int c = col[e];
        int r = row[e];
        int p = atomicAdd(&g_cnt[c], 1);
        int pos = g_rowptr[c] + p;
        g_esrc[pos] = r;
        g_ew[pos] = g_deginv[r];   // norm = deg_inv[source]; deg over destinations
    }
}

// ---------------- fused node-feature pipeline ----------------
// block = 256 threads handles 64 nodes. Dynamic smem: sX[64*128] | sB[64*192]
__global__ void __launch_bounds__(256)
k_node(const float* __restrict__ x, const int* __restrict__ tsteps,
       const float* __restrict__ Wi, const float* __restrict__ bi,
       const float* __restrict__ WQ, const float* __restrict__ bQ,
       const float* __restrict__ WK, const float* __restrict__ bK,
       const float* __restrict__ WV, const float* __restrict__ bV,
       const float* __restrict__ hopwise) {
    extern __shared__ float sm[];
    float* sX = sm;               // 8192 floats
    float* sB = sm + 64 * 128;    // 12288 floats: h | K | V
    const int t = threadIdx.x;
    const int nb = blockIdx.x * 64;
    const int lane = t & 31, wid = t >> 5;

    // ---- load x tile (float4, coalesced) ----
    {
        const float4* xv = (const float4*)x;
        float4* sxv = (float4*)sX;
#pragma unroll
        for (int i = 0; i < 8; i++) {
            int idx = t + 256 * i;      // float4 index in tile (2048 total)
            int n = idx >> 5;           // 32 float4 per row
            int c4 = idx & 31;
            float4 v = make_float4(0.f, 0.f, 0.f, 0.f);
            if (nb + n < NN) v = __ldg(xv + (size_t)(nb + n) * 32 + c4);
            sxv[idx] = v;
        }
    }
    __syncthreads();

    // ---- h = relu(sX @ Wi + bi + temb[ts]) -> sB[0:4096] ----
    {
        float acc[8][2];
        {
            float2 b = __ldg((const float2*)bi + lane);
#pragma unroll
            for (int i = 0; i < 8; i++) { acc[i][0] = b.x; acc[i][1] = b.y; }
        }
        for (int k0 = 0; k0 < 128; k0 += 4) {
            float wv[4][2];
#pragma unroll
            for (int r = 0; r < 4; r++) {
                float2 w = __ldg((const float2*)(Wi + (k0 + r) * 64) + lane);
                wv[r][0] = w.x; wv[r][1] = w.y;
            }
#pragma unroll
            for (int i = 0; i < 8; i++) {
                float4 a = *(const float4*)(sX + (wid + 8 * i) * 128 + k0);
#pragma unroll
                for (int c = 0; c < 2; c++) {
                    acc[i][c] = fmaf(a.x, wv[0][c],
                                fmaf(a.y, wv[1][c],
                                fmaf(a.z, wv[2][c],
                                fmaf(a.w, wv[3][c], acc[i][c]))));
                }
            }
        }
#pragma unroll
        for (int i = 0; i < 8; i++) {
            int rowl = wid + 8 * i;
            int g = nb + rowl;
            int ts = (g < NN) ? __ldg(tsteps + g) : 0;
            const float2* te = (const float2*)(g_temb + ts * 64) + lane;
            float2 tv = *te;
#pragma unroll
            for (int c = 0; c < 2; c++) {
                float v = acc[i][c] + ((c == 0) ? tv.x : tv.y);
                v = fmaxf(v, 0.0f);
                sB[rowl * 64 + lane * 2 + c] = v;
            }
        }
    }
    __syncthreads();

    // ---- Q,K,V from h ----
    {
        float aq[8][2], ak[8][2], av[8][2];
        {
            float2 bq = __ldg((const float2*)bQ + lane);
            float2 bk = __ldg((const float2*)bK + lane);
            float2 bv = __ldg((const float2*)bV + lane);
#pragma unroll
            for (int i = 0; i < 8; i++) {
                aq[i][0] = bq.x; aq[i][1] = bq.y;
                ak[i][0] = bk.x; ak[i][1] = bk.y;
                av[i][0] = bv.x; av[i][1] = bv.y;
            }
        }
        for (int k0 = 0; k0 < 64; k0 += 4) {
            float wq[4][2], wk[4][2], wvv[4][2];
#pragma unroll
            for (int r = 0; r < 4; r++) {
                float2 a1 = __ldg((const float2*)(WQ + (k0 + r) * 64) + lane);
                float2 a2 = __ldg((const float2*)(WK + (k0 + r) * 64) + lane);
                float2 a3 = __ldg((const float2*)(WV + (k0 + r) * 64) + lane);
                wq[r][0] = a1.x; wq[r][1] = a1.y;
                wk[r][0] = a2.x; wk[r][1] = a2.y;
                wvv[r][0] = a3.x; wvv[r][1] = a3.y;
            }
#pragma unroll
            for (int i = 0; i < 8; i++) {
                float4 a = *(const float4*)(sB + (wid + 8 * i) * 64 + k0);
#pragma unroll
                for (int c = 0; c < 2; c++) {
                    aq[i][c] = fmaf(a.x, wq[0][c], fmaf(a.y, wq[1][c], fmaf(a.z, wq[2][c], fmaf(a.w, wq[3][c], aq[i][c]))));
                    ak[i][c] = fmaf(a.x, wk[0][c], fmaf(a.y, wk[1][c], fmaf(a.z, wk[2][c], fmaf(a.w, wk[3][c], ak[i][c]))));
                    av[i][c] = fmaf(a.x, wvv[0][c], fmaf(a.y, wvv[1][c], fmaf(a.z, wvv[2][c], fmaf(a.w, wvv[3][c], av[i][c]))));
                }
            }
        }
        __syncthreads();
        float hop0 = __ldg(hopwise);
#pragma unroll
        for (int i = 0; i < 8; i++) {
            int nl = wid + 8 * i;
            int g = nb + nl;
#pragma unroll
            for (int c = 0; c < 2; c++) {
                int cc = lane * 2 + c;
                float q = aq[i][c]; q = (q > 0.f) ? q + 1.f : expf(q);
                float kk = ak[i][c]; kk = (kk > 0.f) ? kk + 1.f : expf(kk);
                float vv = av[i][c];
                sB[4096 + nl * 64 + cc] = kk;
                sB[8192 + nl * 64 + cc] = vv;
                if (g < NN) {
                    g_Q[g * 64 + cc] = q;
                    g_Kp[0][g * 64 + cc] = kk;
                    g_hidden[g * 64 + cc] = vv * hop0;
                }
            }
        }
    }
    __syncthreads();

    // ---- M0[n,h,i,j] = K[n,h,i] * V[n,h,j], stored as half2 ----
    {
        const float* sK = sB + 4096;
        const float* sV = sB + 8192;
        for (int idx = t; idx < 64 * 512; idx += 256) {
            int n = idx >> 9;
            int r2 = idx & 511;           // half2 index within node
            int h = r2 >> 7;
            int rem = r2 & 127;
            int i = rem >> 3;
            int j2 = (rem & 7) * 2;
            int g = nb + n;
            if (g < NN) {
                float kk = sK[n * 64 + h * 16 + i];
                float v0 = sV[n * 64 + h * 16 + j2];
                float v1 = sV[n * 64 + h * 16 + j2 + 1];
                g_Mh[0][(size_t)g * 512 + r2] = __floats2half2_rn(kk * v0, kk * v1);
            }
        }
    }
}

// ---------------- fused propagation + H/C + hidden update ----------------
// TWO warps per destination node; warp `half` owns heads {2*half, 2*half+1}.
// Edge loop processes TWO edges per iteration with next-pair index prefetch:
// 4-6 independent L2 loads in flight per warp instead of ~2.
__global__ void __launch_bounds__(256)
k_prop(int cur, int hop, int last,
       const float* __restrict__ hopwise, const float* __restrict__ headwise) {
    int warp = (blockIdx.x * 256 + threadIdx.x) >> 5;
    int node = warp >> 1;
    int half = warp & 1;
    int lane = threadIdx.x & 31;
    if (node >= NN) return;
    int s = g_rowptr[node], e = g_rowptr[node + 1];
    const uint4* Mc = (const uint4*)g_Mh[cur];
    const float* Kc = g_Kp[cur];

    float acc[2][8];
#pragma unroll
    for (int u = 0; u < 2; u++)
#pragma unroll
        for (int c = 0; c < 8; c++) acc[u][c] = 0.f;
    float4 ack = make_float4(0.f, 0.f, 0.f, 0.f);

    // ---- software-pipelined, 2 edges per iteration ----
    int p = s;
    int r0 = 0, r1 = 0; float w0 = 0.f, w1 = 0.f;
    if (p < e)     { r0 = __ldg(g_esrc + p);     w0 = __ldg(g_ew + p); }
    if (p + 1 < e) { r1 = __ldg(g_esrc + p + 1); w1 = __ldg(g_ew + p + 1); }
    while (p < e) {
        const bool have1 = (p + 1 < e);
        // issue all loads for this chunk up front
        const uint4* s0 = Mc + (size_t)r0 * 128 + 64 * half + lane;
        uint4 a0 = __ldg(s0);
        uint4 b0 = __ldg(s0 + 32);
        float4 k0 = make_float4(0.f, 0.f, 0.f, 0.f);
        if (lane < 8) k0 = __ldg((const float4*)(Kc + r0 * 64 + half * 32) + lane);
        uint4 a1 = make_uint4(0u, 0u, 0u, 0u), b1 = make_uint4(0u, 0u, 0u, 0u);
        float4 k1 = make_float4(0.f, 0.f, 0.f, 0.f);
        if (have1) {
            const uint4* s1 = Mc + (size_t)r1 * 128 + 64 * half + lane;
            a1 = __ldg(s1);
            b1 = __ldg(s1 + 32);
            if (lane < 8) k1 = __ldg((const float4*)(Kc + r1 * 64 + half * 32) + lane);
        }
        // prefetch next chunk's indices while the data loads are in flight
        int nr0 = 0, nr1 = 0; float nw0 = 0.f, nw1 = 0.f;
        if (p + 2 < e) { nr0 = __ldg(g_esrc + p + 2); nw0 = __ldg(g_ew + p + 2); }
        if (p + 3 < e) { nr1 = __ldg(g_esrc + p + 3); nw1 = __ldg(g_ew + p + 3); }

        // FMAs for edge 0
        {
            const __half2* hv = (const __half2*)&a0;
#pragma unroll
            for (int c2 = 0; c2 < 4; c2++) {
                float2 f = __half22float2(hv[c2]);
                acc[0][2 * c2]     = fmaf(f.x, w0, acc[0][2 * c2]);
                acc[0][2 * c2 + 1] = fmaf(f.y, w0, acc[0][2 * c2 + 1]);
            }
            const __half2* hw = (const __half2*)&b0;
#pragma unroll
            for (int c2 = 0; c2 < 4; c2++) {
                float2 f = __half22float2(hw[c2]);
                acc[1][2 * c2]     = fmaf(f.x, w0, acc[1][2 * c2]);
                acc[1][2 * c2 + 1] = fmaf(f.y, w0, acc[1][2 * c2 + 1]);
            }
            ack.x = fmaf(k0.x, w0, ack.x);
            ack.y = fmaf(k0.y, w0, ack.y);
            ack.z = fmaf(k0.z, w0, ack.z);
            ack.w = fmaf(k0.w, w0, ack.w);
        }
        // FMAs for edge 1
        if (have1) {
            const __half2* hv = (const __half2*)&a1;
#pragma unroll
            for (int c2 = 0; c2 < 4; c2++) {
                float2 f = __half22float2(hv[c2]);
                acc[0][2 * c2]     = fmaf(f.x, w1, acc[0][2 * c2]);
                acc[0][2 * c2 + 1] = fmaf(f.y, w1, acc[0][2 * c2 + 1]);
            }
            const __half2* hw = (const __half2*)&b1;
#pragma unroll
            for (int c2 = 0; c2 < 4; c2++) {
                float2 f = __half22float2(hw[c2]);
                acc[1][2 * c2]     = fmaf(f.x, w1, acc[1][2 * c2]);
                acc[1][2 * c2 + 1] = fmaf(f.y, w1, acc[1][2 * c2 + 1]);
            }
            ack.x = fmaf(k1.x, w1, ack.x);
            ack.y = fmaf(k1.y, w1, ack.y);
            ack.z = fmaf(k1.z, w1, ack.z);
            ack.w = fmaf(k1.w, w1, ack.w);
        }
        p += 2;
        r0 = nr0; w0 = nw0; r1 = nr1; w1 = nw1;
    }

    // write propagated M/Kf (skip on last hop — nobody consumes them)
    if (!last) {
        uint4* dst = (uint4*)g_Mh[cur ^ 1] + (size_t)node * 128 + 64 * half + lane;
#pragma unroll
        for (int u = 0; u < 2; u++) {
            uint4 o;
            __half2* ho = (__half2*)&o;
#pragma unroll
            for (int c2 = 0; c2 < 4; c2++)
                ho[c2] = __floats2half2_rn(acc[u][2 * c2], acc[u][2 * c2 + 1]);
            dst[32 * u] = o;
        }
        if (lane < 8) ((float4*)(g_Kp[cur ^ 1] + node * 64 + half * 32))[lane] = ack;
    }

    // ---- C[h] = Q[h,:].Kf[h,:] on lanes 0..7 ----
    const float* Q = g_Q + node * 64;
    float cpart = 0.f;
    if (lane < 8) {
        float4 qc = __ldg((const float4*)(Q + half * 32) + lane);
        cpart = qc.x * ack.x + qc.y * ack.y + qc.z * ack.z + qc.w * ack.w;
    }
    cpart += __shfl_xor_sync(0xFFFFFFFFu, cpart, 1);
    cpart += __shfl_xor_sync(0xFFFFFFFFu, cpart, 2);
    // lanes 0-3 hold C[local 0], lanes 4-7 hold C[local 1]

    // ---- H[u][j] = sum_i Q[gh,i]*M[gh,i,j]; i = lane>>1, j = 8*(lane&1)+c ----
    float hp[2][8];
    {
        int i = lane >> 1;
#pragma unroll
        for (int u = 0; u < 2; u++) {
            float qh = __ldg(Q + (2 * half + u) * 16 + i);
#pragma unroll
            for (int c = 0; c < 8; c++) hp[u][c] = qh * acc[u][c];
        }
    }
#pragma unroll
    for (int m = 2; m <= 16; m <<= 1) {
#pragma unroll
        for (int u = 0; u < 2; u++)
#pragma unroll
            for (int c = 0; c < 8; c++)
                hp[u][c] += __shfl_xor_sync(0xFFFFFFFFu, hp[u][c], m);
    }

    // gamma[h] = hopwise[hop+1] * softmax_over_heads(headwise[:,hop])[h]
    float hw0 = __ldg(headwise + 0 * KHOP + hop);
    float hw1 = __ldg(headwise + 1 * KHOP + hop);
    float hw2 = __ldg(headwise + 2 * KHOP + hop);
    float hw3 = __ldg(headwise + 3 * KHOP + hop);
    float mx = fmaxf(fmaxf(hw0, hw1), fmaxf(hw2, hw3));
    float e0 = expf(hw0 - mx), e1 = expf(hw1 - mx), e2 = expf(hw2 - mx), e3 = expf(hw3 - mx);
    float ssum = e0 + e1 + e2 + e3;
    float hopw = __ldg(hopwise + hop + 1);

    float Csel = __shfl_sync(0xFFFFFFFFu, cpart, ((lane >> 1) & 1) * 4) + 1e-5f;

    if (lane < 4) {
        int lh = lane >> 1;            // local head
        int gh = 2 * half + lh;        // global head
        int jb = (lane & 1) * 8;
        float eh = (gh == 0) ? e0 : (gh == 1) ? e1 : (gh == 2) ? e2 : e3;
        float scale = hopw * (eh / ssum) / Csel;
        float hv[8];
#pragma unroll
        for (int c = 0; c < 8; c++) hv[c] = (lh == 0) ? hp[0][c] : hp[1][c];
        float* hd = g_hidden + node * 64 + gh * 16 + jb;
        float4 a = *(float4*)hd;
        float4 b = *(float4*)(hd + 4);
        a.x += scale * hv[0]; a.y += scale * hv[1]; a.z += scale * hv[2]; a.w += scale * hv[3];
        b.x += scale * hv[4]; b.y += scale * hv[5]; b.z += scale * hv[6]; b.w += scale * hv[7];
        *(float4*)hd = a;
        *(float4*)(hd + 4) = b;
    }
}

// ---------------- output projection: hidden[N,64] @ Wo[64,16] + bo ----------------
__global__ void k_proj(const float* __restrict__ Wo, const float* __restrict__ bo,
                       float* __restrict__ outHid) {
    int idx = blockIdx.x * blockDim.x + threadIdx.x;
    if (idx >= NN * 16) return;
    int n = idx >> 4, j = idx & 15;
    float acc = __ldg(bo + j);
    const float* hd = g_hidden + n * 64;
#pragma unroll
    for (int k = 0; k < 64; k++) acc = fmaf(hd[k], __ldg(Wo + k * 16 + j), acc);
    outHid[idx] = acc;
}

// ---------------- edge regression head ----------------
__global__ void k_edge(const int* __restrict__ fsrc, const int* __restrict__ fdst,
                       const float* __restrict__ hid,
                       const float* __restrict__ Wf1, const float* __restrict__ bf1,
                       const float* __restrict__ Wf2, const float* __restrict__ bf2,
                       float* __restrict__ out) {
    __shared__ float sW1[512];
    __shared__ float sb1[16];
    __shared__ float sW2[16];
    __shared__ float sb2;
    int t = threadIdx.x;
    sW1[t] = __ldg(Wf1 + t);
    sW1[t + 256] = __ldg(Wf1 + t + 256);
    if (t < 16) { sb1[t] = __ldg(bf1 + t); sW2[t] = __ldg(Wf2 + t); }
    if (t == 0) sb2 = __ldg(bf2);
    __syncthreads();
    int idx = blockIdx.x * blockDim.x + t;
    if (idx >= FEE) return;
    int s = fsrc[idx], d = fdst[idx];
    float he[32];
    {
        const float4* ps = (const float4*)(hid + s * 16);
        const float4* pd = (const float4*)(hid + d * 16);
#pragma unroll
        for (int u = 0; u < 4; u++) {
            float4 a = __ldg(ps + u);
            he[4 * u + 0] = a.x; he[4 * u + 1] = a.y; he[4 * u + 2] = a.z; he[4 * u + 3] = a.w;
            float4 b = __ldg(pd + u);
            he[16 + 4 * u + 0] = b.x; he[16 + 4 * u + 1] = b.y; he[16 + 4 * u + 2] = b.z; he[16 + 4 * u + 3] = b.w;
        }
    }
    float o = sb2;
#pragma unroll
    for (int j = 0; j < 16; j++) {
        float a = sb1[j];
#pragma unroll
        for (int k = 0; k < 32; k++) a = fmaf(he[k], sW1[k * 16 + j], a);
        a = a / (1.0f + expf(-a));  // silu
        o = fmaf(a, sW2[j], o);
    }
    out[idx] = o;
}

// ---------------- launch ----------------
extern "C" void kernel_launch(void* const* d_in, const int* in_sizes, int n_in,
                              void* d_out, int out_size) {
    (void)in_sizes; (void)n_in; (void)out_size;
    const float* x      = (const float*)d_in[0];
    const int*   ei     = (const int*)d_in[1];
    const int*   fei    = (const int*)d_in[2];
    const int*   tsteps = (const int*)d_in[3];
    const float* Wi  = (const float*)d_in[4];
    const float* bi  = (const float*)d_in[5];
    const float* Wt1 = (const float*)d_in[6];
    const float* bt1 = (const float*)d_in[7];
    const float* Wt2 = (const float*)d_in[8];
    const float* bt2 = (const float*)d_in[9];
    const float* WQ  = (const float*)d_in[10];
    const float* bQ  = (const float*)d_in[11];
    const float* WK  = (const float*)d_in[12];
    const float* bK  = (const float*)d_in[13];
    const float* WV  = (const float*)d_in[14];
    const float* bV  = (const float*)d_in[15];
    const float* Wo  = (const float*)d_in[16];
    const float* bo  = (const float*)d_in[17];
    const float* hopwise  = (const float*)d_in[18];
    const float* headwise = (const float*)d_in[19];
    const float* Wf1 = (const float*)d_in[20];
    const float* bf1 = (const float*)d_in[21];
    const float* Wf2 = (const float*)d_in[22];
    const float* bf2 = (const float*)d_in[23];

    float* out = (float*)d_out;
    float* outHid = out + FEE;

    const int* row = ei;
    const int* col = ei + EE;
    const int* fsrc = fei;
    const int* fdst = fei + FEE;

    k_temb<<<128, 64>>>(Wt1, bt1, Wt2, bt2);
    k_init<<<(NN + 255) / 256, 256>>>();
    k_hist<<<(EE + 255) / 256, 256>>>(col);
    k_scanA<<<79, 256>>>();
    k_scanB<<<1, 128>>>();
    k_scanC<<<79, 256>>>();
    k_fill<<<(EE + 255) / 256, 256>>>(row, col);

    cudaFuncSetAttribute(k_node, cudaFuncAttributeMaxDynamicSharedMemorySize, 81920);
    k_node<<<(NN + 63) / 64, 256, 81920>>>(x, tsteps, Wi, bi,
                                           WQ, bQ, WK, bK, WV, bV, hopwise);

    int cur = 0;
    for (int hop = 0; hop < KHOP; hop++) {
        k_prop<<<(NN * 64 + 255) / 256, 256>>>(cur, hop, hop == KHOP - 1, hopwise, headwise);
        cur ^= 1;
    }

    k_proj<<<(NN * 16 + 255) / 256, 256>>>(Wo, bo, outHid);
    k_edge<<<(FEE + 255) / 256, 256>>>(fsrc, fdst, outHid, Wf1, bf1, Wf2, bf2, out);
}